// round 15
// baseline (speedup 1.0000x reference)
#include <cuda_runtime.h>

#define F_DIM 160
#define H_DIM 128
#define C_DIM 10
#define BM    128
#define BK    16
#define NKT   (F_DIM / BK)        // 10
#define AS_LD 132                 // padded leading dim for A tiles
#define AS_BUF (BK * AS_LD)       // 2112 floats per buffer
#define W_SM  (F_DIM * H_DIM)     // 20480 floats
#define WSP_LD 12                 // padded Ws row (10 -> 12)

#define SMEM1_BYTES ((W_SM + 2 * AS_BUF) * 4)                          // 98816
#define SMEM2_BYTES ((W_SM + 2 * AS_BUF + H_DIM * WSP_LD + 16) * 4)    // 105088

// ---- scratch / globals (allowed: __device__ global arrays) ----
__device__ float g_out1[262144 * H_DIM];     // raw out1 (pre-noise), 128MB
__device__ unsigned g_max_bits;
__device__ unsigned g_min_bits;

// ---- f32x2 packed-FMA helpers (Blackwell FFMA2, PTX-only) ----
__device__ __forceinline__ unsigned long long fdup(float a) {
    unsigned long long r;
    asm("mov.b64 %0, {%1, %1};" : "=l"(r) : "f"(a));
    return r;
}
__device__ __forceinline__ void ffma2(unsigned long long &c,
                                      unsigned long long a,
                                      unsigned long long b) {
    asm("fma.rn.f32x2 %0, %1, %2, %0;" : "+l"(c) : "l"(a), "l"(b));
}
__device__ __forceinline__ float2 unpack2(unsigned long long v) {
    float2 r;
    asm("mov.b64 {%0, %1}, %2;" : "=f"(r.x), "=f"(r.y) : "l"(v));
    return r;
}

__device__ __forceinline__ void store_a8(float* dst, float4 p0, float4 p1) {
    dst[0 * AS_LD] = p0.x; dst[1 * AS_LD] = p0.y;
    dst[2 * AS_LD] = p0.z; dst[3 * AS_LD] = p0.w;
    dst[4 * AS_LD] = p1.x; dst[5 * AS_LD] = p1.y;
    dst[6 * AS_LD] = p1.z; dst[7 * AS_LD] = p1.w;
}

// acc[i][j] is an f32x2 pair: cols (tx*8 + 2j, tx*8 + 2j + 1), row row0 + ty*8 + i.
// Computes X[128 rows, 160] @ Wg[160, 128] into acc. W fully staged in shared,
// A tiles double-buffered. Ends WITHOUT a trailing __syncthreads().
__device__ __forceinline__ void gemm_tile(const float* __restrict__ X,
                                          const float* __restrict__ Wg,
                                          float* Wst, float* As,
                                          int row0, int tid, int tx, int ty,
                                          unsigned long long (&acc)[8][4]) {
    // Stage full W (160x128) into shared
    #pragma unroll
    for (int it = 0; it < W_SM / (256 * 4); it++) {
        int idx = (it * 256 + tid) * 4;
        *(float4*)&Wst[idx] = *(const float4*)&Wg[idx];
    }

    const int arow = tid >> 1;           // 0..127
    const int kh   = (tid & 1) << 3;     // 0 or 8
    const float* xa = X + (size_t)(row0 + arow) * F_DIM + kh;

    // Preload A tile 0
    float4 p0 = *(const float4*)(xa);
    float4 p1 = *(const float4*)(xa + 4);
    store_a8(As + kh * AS_LD + arow, p0, p1);

    #pragma unroll
    for (int i = 0; i < 8; i++)
        #pragma unroll
        for (int j = 0; j < 4; j++)
            acc[i][j] = 0ull;

    __syncthreads();

    int buf = 0;
    #pragma unroll 1
    for (int kt = 0; kt < NKT; kt++) {
        float4 n0, n1;
        if (kt < NKT - 1) {
            n0 = *(const float4*)(xa + (kt + 1) * BK);
            n1 = *(const float4*)(xa + (kt + 1) * BK + 4);
        }
        const float* Asb = As + buf * AS_BUF + ty * 8;
        const float* Bb  = Wst + kt * BK * H_DIM + tx * 8;
        #pragma unroll
        for (int k = 0; k < BK; k++) {
            float4 av0 = *(const float4*)(Asb + k * AS_LD);
            float4 av1 = *(const float4*)(Asb + k * AS_LD + 4);
            ulonglong2 bq0 = *(const ulonglong2*)(Bb + k * H_DIM);
            ulonglong2 bq1 = *(const ulonglong2*)(Bb + k * H_DIM + 4);
            unsigned long long bb[4] = {bq0.x, bq0.y, bq1.x, bq1.y};
            float aa[8] = {av0.x, av0.y, av0.z, av0.w,
                           av1.x, av1.y, av1.z, av1.w};
            #pragma unroll
            for (int i = 0; i < 8; i++) {
                unsigned long long ad = fdup(aa[i]);
                #pragma unroll
                for (int j = 0; j < 4; j++)
                    ffma2(acc[i][j], ad, bb[j]);
            }
        }
        if (kt < NKT - 1) {
            store_a8(As + (buf ^ 1) * AS_BUF + kh * AS_LD + arow, n0, n1);
            __syncthreads();
            buf ^= 1;
        }
    }
}

__global__ void init_minmax_kernel() {
    g_max_bits = 0u;             // norms are >= 0
    g_min_bits = 0x7f800000u;    // +inf
}

// Phase 1: out1_raw = x1 @ W1 + b1 -> g_out1; row L1 norms -> global max/min
__global__ void __launch_bounds__(256, 2)
phase1_kernel(const float* __restrict__ x1, const float* __restrict__ W1,
              const float* __restrict__ b1) {
    extern __shared__ float sm[];
    float* Wst = sm;
    float* As  = sm + W_SM;
    __shared__ unsigned s_mx, s_mn;

    const int tid = threadIdx.x;
    const int tx = tid & 15, ty = tid >> 4;
    const int row0 = blockIdx.x * BM;

    if (tid == 0) { s_mx = 0u; s_mn = 0x7f800000u; }

    unsigned long long acc[8][4];
    gemm_tile(x1, W1, Wst, As, row0, tid, tx, ty, acc);

    const float4 bb0 = *(const float4*)(b1 + tx * 8);
    const float4 bb1 = *(const float4*)(b1 + tx * 8 + 4);

    float rmax = -3.4e38f, rmin = 3.4e38f;
    #pragma unroll
    for (int i = 0; i < 8; i++) {
        float2 c0 = unpack2(acc[i][0]);
        float2 c1 = unpack2(acc[i][1]);
        float2 c2 = unpack2(acc[i][2]);
        float2 c3 = unpack2(acc[i][3]);
        float4 s0 = make_float4(c0.x + bb0.x, c0.y + bb0.y, c1.x + bb0.z, c1.y + bb0.w);
        float4 s1 = make_float4(c2.x + bb1.x, c2.y + bb1.y, c3.x + bb1.z, c3.y + bb1.w);
        const int row = row0 + ty * 8 + i;
        float* op = g_out1 + (size_t)row * H_DIM + tx * 8;
        *(float4*)op = s0;
        *(float4*)(op + 4) = s1;
        float rs = fabsf(s0.x) + fabsf(s0.y) + fabsf(s0.z) + fabsf(s0.w)
                 + fabsf(s1.x) + fabsf(s1.y) + fabsf(s1.z) + fabsf(s1.w);
        rs += __shfl_xor_sync(0xffffffffu, rs, 1);
        rs += __shfl_xor_sync(0xffffffffu, rs, 2);
        rs += __shfl_xor_sync(0xffffffffu, rs, 4);
        rs += __shfl_xor_sync(0xffffffffu, rs, 8);
        rmax = fmaxf(rmax, rs);
        rmin = fminf(rmin, rs);
    }
    if (tx == 0) {
        atomicMax(&s_mx, __float_as_uint(rmax));
        atomicMin(&s_mn, __float_as_uint(rmin));
    }
    __syncthreads();
    if (tid == 0) {
        atomicMax(&g_max_bits, s_mx);
        atomicMin(&g_min_bits, s_mn);
    }
}

// Phase 2: out2 = x2@W2+b2; out1 = (g_out1 + noise*mul)*rr_mask;
// server = min(out1,out2); out = server @ Ws + bs
__global__ void __launch_bounds__(256, 2)
phase2_kernel(const float* __restrict__ x2, const float* __restrict__ W2,
              const float* __restrict__ b2, const float* __restrict__ Wsg,
              const float* __restrict__ bsg, const float* __restrict__ noise,
              const float* __restrict__ rr, float* __restrict__ out) {
    extern __shared__ float sm[];
    float* Wst = sm;
    float* As  = sm + W_SM;
    float* WsP = sm + W_SM + 2 * AS_BUF;         // [128][12] padded
    float* bss = WsP + H_DIM * WSP_LD;           // [10]

    const int tid = threadIdx.x;
    const int tx = tid & 15, ty = tid >> 4;
    const int row0 = blockIdx.x * BM;

    // Stage Ws (padded rows) + bs
    for (int idx = tid; idx < H_DIM * C_DIM; idx += 256)
        WsP[(idx / C_DIM) * WSP_LD + (idx % C_DIM)] = Wsg[idx];
    if (tid < C_DIM) bss[tid] = bsg[tid];

    unsigned long long acc[8][4];
    gemm_tile(x2, W2, Wst, As, row0, tid, tx, ty, acc);

    const float sens = __uint_as_float(g_max_bits) - __uint_as_float(g_min_bits);
    const float mul = sens / (4.0f / 30.0f);

    const float4 bb0 = *(const float4*)(b2 + tx * 8);
    const float4 bb1 = *(const float4*)(b2 + tx * 8 + 4);
    float msk[8];
    #pragma unroll
    for (int j = 0; j < 8; j++)
        msk[j] = (rr[tx * 8 + j] < 0.95f) ? 1.0f : 0.0f;

    __syncthreads();            // everyone done reading Wst -> reuse as server tile
    float* s_s = Wst;           // [128][AS_LD]

    #pragma unroll
    for (int i = 0; i < 8; i++) {
        const int row = row0 + ty * 8 + i;
        float2 c0 = unpack2(acc[i][0]);
        float2 c1 = unpack2(acc[i][1]);
        float2 c2 = unpack2(acc[i][2]);
        float2 c3 = unpack2(acc[i][3]);
        float o2[8] = {c0.x + bb0.x, c0.y + bb0.y, c1.x + bb0.z, c1.y + bb0.w,
                       c2.x + bb1.x, c2.y + bb1.y, c3.x + bb1.z, c3.y + bb1.w};
        const float* o1p = g_out1 + (size_t)row * H_DIM + tx * 8;
        float4 oa = *(const float4*)o1p, ob = *(const float4*)(o1p + 4);
        const float* np = noise + (size_t)row * H_DIM + tx * 8;
        float4 na = *(const float4*)np, nb = *(const float4*)(np + 4);
        float o1[8] = {oa.x, oa.y, oa.z, oa.w, ob.x, ob.y, ob.z, ob.w};
        float nn[8] = {na.x, na.y, na.z, na.w, nb.x, nb.y, nb.z, nb.w};
        float s[8];
        #pragma unroll
        for (int j = 0; j < 8; j++)
            s[j] = fminf((o1[j] + nn[j] * mul) * msk[j], o2[j]);
        float* sp = s_s + (ty * 8 + i) * AS_LD + tx * 8;
        *(float4*)sp = make_float4(s[0], s[1], s[2], s[3]);
        *(float4*)(sp + 4) = make_float4(s[4], s[5], s[6], s[7]);
    }
    __syncthreads();

    // Fused head: server[128,128] @ Ws[128,10] + bs  (one row per thread, 128 active)
    if (tid < BM) {
        const float* srow = s_s + tid * AS_LD;
        float p[10];
        #pragma unroll
        for (int c = 0; c < 10; c++) p[c] = 0.0f;
        #pragma unroll 4
        for (int k = 0; k < H_DIM; k++) {
            float sv = srow[k];
            float4 w0 = *(const float4*)&WsP[k * WSP_LD];
            float4 w1 = *(const float4*)&WsP[k * WSP_LD + 4];
            float2 w2 = *(const float2*)&WsP[k * WSP_LD + 8];
            p[0] = fmaf(sv, w0.x, p[0]); p[1] = fmaf(sv, w0.y, p[1]);
            p[2] = fmaf(sv, w0.z, p[2]); p[3] = fmaf(sv, w0.w, p[3]);
            p[4] = fmaf(sv, w1.x, p[4]); p[5] = fmaf(sv, w1.y, p[5]);
            p[6] = fmaf(sv, w1.z, p[6]); p[7] = fmaf(sv, w1.w, p[7]);
            p[8] = fmaf(sv, w2.x, p[8]); p[9] = fmaf(sv, w2.y, p[9]);
        }
        float* op = out + (size_t)(row0 + tid) * C_DIM;
        #pragma unroll
        for (int c = 0; c < 10; c++) op[c] = p[c] + bss[c];
    }
}

extern "C" void kernel_launch(void* const* d_in, const int* in_sizes, int n_in,
                              void* d_out, int out_size) {
    const float* x1    = (const float*)d_in[0];
    const float* x2    = (const float*)d_in[1];
    const float* W1    = (const float*)d_in[2];
    const float* b1    = (const float*)d_in[3];
    const float* W2    = (const float*)d_in[4];
    const float* b2    = (const float*)d_in[5];
    const float* Ws    = (const float*)d_in[6];
    const float* bs    = (const float*)d_in[7];
    const float* noise = (const float*)d_in[8];
    const float* rr    = (const float*)d_in[9];
    float* out = (float*)d_out;

    const int B = in_sizes[0] / F_DIM;   // 262144
    const int grid = B / BM;             // 2048

    cudaFuncSetAttribute(phase1_kernel,
                         cudaFuncAttributeMaxDynamicSharedMemorySize, SMEM1_BYTES);
    cudaFuncSetAttribute(phase2_kernel,
                         cudaFuncAttributeMaxDynamicSharedMemorySize, SMEM2_BYTES);

    init_minmax_kernel<<<1, 1>>>();
    phase1_kernel<<<grid, 256, SMEM1_BYTES>>>(x1, W1, b1);
    phase2_kernel<<<grid, 256, SMEM2_BYTES>>>(x2, W2, b2, Ws, bs, noise, rr, out);
}

// round 16
// speedup vs baseline: 1.0008x; 1.0008x over previous
#include <cuda_runtime.h>

#define F_DIM 160
#define H_DIM 128
#define C_DIM 10
#define BM    128
#define BK    16
#define NKT   (F_DIM / BK)        // 10
#define AS_LD 132                 // padded leading dim for A tiles
#define AS_BUF (BK * AS_LD)       // 2112 floats per buffer
#define W_SM  (F_DIM * H_DIM)     // 20480 floats
#define WSP_LD 12                 // padded Ws row (10 -> 12)

#define SMEM1_BYTES ((W_SM + 2 * AS_BUF) * 4)                          // 98816
#define SMEM2_BYTES ((W_SM + 2 * AS_BUF + H_DIM * WSP_LD + 16) * 4)    // 105088

// ---- scratch / globals (allowed: __device__ global arrays) ----
__device__ float g_out1[262144 * H_DIM];     // raw out1 (pre-noise), 128MB
__device__ unsigned g_max_bits;
__device__ unsigned g_min_bits;

// ---- f32x2 packed-FMA helpers (Blackwell FFMA2, PTX-only) ----
__device__ __forceinline__ unsigned long long fdup(float a) {
    unsigned long long r;
    asm("mov.b64 %0, {%1, %1};" : "=l"(r) : "f"(a));
    return r;
}
__device__ __forceinline__ void ffma2(unsigned long long &c,
                                      unsigned long long a,
                                      unsigned long long b) {
    asm("fma.rn.f32x2 %0, %1, %2, %0;" : "+l"(c) : "l"(a), "l"(b));
}
__device__ __forceinline__ float2 unpack2(unsigned long long v) {
    float2 r;
    asm("mov.b64 {%0, %1}, %2;" : "=f"(r.x), "=f"(r.y) : "l"(v));
    return r;
}

__device__ __forceinline__ void store_a8(float* dst, float4 p0, float4 p1) {
    dst[0 * AS_LD] = p0.x; dst[1 * AS_LD] = p0.y;
    dst[2 * AS_LD] = p0.z; dst[3 * AS_LD] = p0.w;
    dst[4 * AS_LD] = p1.x; dst[5 * AS_LD] = p1.y;
    dst[6 * AS_LD] = p1.z; dst[7 * AS_LD] = p1.w;
}

// acc[i][j] is an f32x2 pair: cols (tx*8 + 2j, tx*8 + 2j + 1), row row0 + ty*8 + i.
// Computes X[128 rows, 160] @ Wg[160, 128] into acc. W fully staged in shared,
// A tiles double-buffered. Ends WITHOUT a trailing __syncthreads().
__device__ __forceinline__ void gemm_tile(const float* __restrict__ X,
                                          const float* __restrict__ Wg,
                                          float* Wst, float* As,
                                          int row0, int tid, int tx, int ty,
                                          unsigned long long (&acc)[8][4]) {
    // Stage full W (160x128) into shared
    #pragma unroll
    for (int it = 0; it < W_SM / (256 * 4); it++) {
        int idx = (it * 256 + tid) * 4;
        *(float4*)&Wst[idx] = *(const float4*)&Wg[idx];
    }

    const int arow = tid >> 1;           // 0..127
    const int kh   = (tid & 1) << 3;     // 0 or 8
    const float* xa = X + (size_t)(row0 + arow) * F_DIM + kh;

    // Preload A tile 0
    float4 p0 = *(const float4*)(xa);
    float4 p1 = *(const float4*)(xa + 4);
    store_a8(As + kh * AS_LD + arow, p0, p1);

    #pragma unroll
    for (int i = 0; i < 8; i++)
        #pragma unroll
        for (int j = 0; j < 4; j++)
            acc[i][j] = 0ull;

    __syncthreads();

    int buf = 0;
    #pragma unroll 1
    for (int kt = 0; kt < NKT; kt++) {
        float4 n0, n1;
        if (kt < NKT - 1) {
            n0 = *(const float4*)(xa + (kt + 1) * BK);
            n1 = *(const float4*)(xa + (kt + 1) * BK + 4);
        }
        const float* Asb = As + buf * AS_BUF + ty * 8;
        const float* Bb  = Wst + kt * BK * H_DIM + tx * 8;
        #pragma unroll
        for (int k = 0; k < BK; k++) {
            float4 av0 = *(const float4*)(Asb + k * AS_LD);
            float4 av1 = *(const float4*)(Asb + k * AS_LD + 4);
            ulonglong2 bq0 = *(const ulonglong2*)(Bb + k * H_DIM);
            ulonglong2 bq1 = *(const ulonglong2*)(Bb + k * H_DIM + 4);
            unsigned long long bb[4] = {bq0.x, bq0.y, bq1.x, bq1.y};
            float aa[8] = {av0.x, av0.y, av0.z, av0.w,
                           av1.x, av1.y, av1.z, av1.w};
            #pragma unroll
            for (int i = 0; i < 8; i++) {
                unsigned long long ad = fdup(aa[i]);
                #pragma unroll
                for (int j = 0; j < 4; j++)
                    ffma2(acc[i][j], ad, bb[j]);
            }
        }
        if (kt < NKT - 1) {
            store_a8(As + (buf ^ 1) * AS_BUF + kh * AS_LD + arow, n0, n1);
            __syncthreads();
            buf ^= 1;
        }
    }
}

__global__ void init_minmax_kernel() {
    g_max_bits = 0u;             // norms are >= 0
    g_min_bits = 0x7f800000u;    // +inf
}

// Phase 1: out1_raw = x1 @ W1 + b1 -> g_out1; row L1 norms -> global max/min
__global__ void __launch_bounds__(256, 2)
phase1_kernel(const float* __restrict__ x1, const float* __restrict__ W1,
              const float* __restrict__ b1) {
    extern __shared__ float sm[];
    float* Wst = sm;
    float* As  = sm + W_SM;
    __shared__ unsigned s_mx, s_mn;

    const int tid = threadIdx.x;
    const int tx = tid & 15, ty = tid >> 4;
    const int row0 = blockIdx.x * BM;

    if (tid == 0) { s_mx = 0u; s_mn = 0x7f800000u; }

    unsigned long long acc[8][4];
    gemm_tile(x1, W1, Wst, As, row0, tid, tx, ty, acc);

    const float4 bb0 = *(const float4*)(b1 + tx * 8);
    const float4 bb1 = *(const float4*)(b1 + tx * 8 + 4);

    float rmax = -3.4e38f, rmin = 3.4e38f;
    #pragma unroll
    for (int i = 0; i < 8; i++) {
        float2 c0 = unpack2(acc[i][0]);
        float2 c1 = unpack2(acc[i][1]);
        float2 c2 = unpack2(acc[i][2]);
        float2 c3 = unpack2(acc[i][3]);
        float4 s0 = make_float4(c0.x + bb0.x, c0.y + bb0.y, c1.x + bb0.z, c1.y + bb0.w);
        float4 s1 = make_float4(c2.x + bb1.x, c2.y + bb1.y, c3.x + bb1.z, c3.y + bb1.w);
        const int row = row0 + ty * 8 + i;
        float* op = g_out1 + (size_t)row * H_DIM + tx * 8;
        *(float4*)op = s0;
        *(float4*)(op + 4) = s1;
        float rs = fabsf(s0.x) + fabsf(s0.y) + fabsf(s0.z) + fabsf(s0.w)
                 + fabsf(s1.x) + fabsf(s1.y) + fabsf(s1.z) + fabsf(s1.w);
        rs += __shfl_xor_sync(0xffffffffu, rs, 1);
        rs += __shfl_xor_sync(0xffffffffu, rs, 2);
        rs += __shfl_xor_sync(0xffffffffu, rs, 4);
        rs += __shfl_xor_sync(0xffffffffu, rs, 8);
        rmax = fmaxf(rmax, rs);
        rmin = fminf(rmin, rs);
    }
    if (tx == 0) {
        atomicMax(&s_mx, __float_as_uint(rmax));
        atomicMin(&s_mn, __float_as_uint(rmin));
    }
    __syncthreads();
    if (tid == 0) {
        atomicMax(&g_max_bits, s_mx);
        atomicMin(&g_min_bits, s_mn);
    }
}

// Phase 2: out2 = x2@W2+b2; out1 = (g_out1 + noise*mul)*rr_mask;
// server = min(out1,out2); out = server @ Ws + bs
__global__ void __launch_bounds__(256, 2)
phase2_kernel(const float* __restrict__ x2, const float* __restrict__ W2,
              const float* __restrict__ b2, const float* __restrict__ Wsg,
              const float* __restrict__ bsg, const float* __restrict__ noise,
              const float* __restrict__ rr, float* __restrict__ out) {
    extern __shared__ float sm[];
    float* Wst = sm;
    float* As  = sm + W_SM;
    float* WsP = sm + W_SM + 2 * AS_BUF;         // [128][12] padded
    float* bss = WsP + H_DIM * WSP_LD;           // [10]

    const int tid = threadIdx.x;
    const int tx = tid & 15, ty = tid >> 4;
    const int row0 = blockIdx.x * BM;

    // Stage Ws (padded rows) + bs
    for (int idx = tid; idx < H_DIM * C_DIM; idx += 256)
        WsP[(idx / C_DIM) * WSP_LD + (idx % C_DIM)] = Wsg[idx];
    if (tid < C_DIM) bss[tid] = bsg[tid];

    unsigned long long acc[8][4];
    gemm_tile(x2, W2, Wst, As, row0, tid, tx, ty, acc);

    const float sens = __uint_as_float(g_max_bits) - __uint_as_float(g_min_bits);
    const float mul = sens / (4.0f / 30.0f);

    const float4 bb0 = *(const float4*)(b2 + tx * 8);
    const float4 bb1 = *(const float4*)(b2 + tx * 8 + 4);
    float msk[8];
    #pragma unroll
    for (int j = 0; j < 8; j++)
        msk[j] = (rr[tx * 8 + j] < 0.95f) ? 1.0f : 0.0f;

    __syncthreads();            // everyone done reading Wst -> reuse as server tile
    float* s_s = Wst;           // [128][AS_LD]

    #pragma unroll
    for (int i = 0; i < 8; i++) {
        const int row = row0 + ty * 8 + i;
        float2 c0 = unpack2(acc[i][0]);
        float2 c1 = unpack2(acc[i][1]);
        float2 c2 = unpack2(acc[i][2]);
        float2 c3 = unpack2(acc[i][3]);
        float o2[8] = {c0.x + bb0.x, c0.y + bb0.y, c1.x + bb0.z, c1.y + bb0.w,
                       c2.x + bb1.x, c2.y + bb1.y, c3.x + bb1.z, c3.y + bb1.w};
        const float* o1p = g_out1 + (size_t)row * H_DIM + tx * 8;
        float4 oa = *(const float4*)o1p, ob = *(const float4*)(o1p + 4);
        const float* np = noise + (size_t)row * H_DIM + tx * 8;
        float4 na = *(const float4*)np, nb = *(const float4*)(np + 4);
        float o1[8] = {oa.x, oa.y, oa.z, oa.w, ob.x, ob.y, ob.z, ob.w};
        float nn[8] = {na.x, na.y, na.z, na.w, nb.x, nb.y, nb.z, nb.w};
        float s[8];
        #pragma unroll
        for (int j = 0; j < 8; j++)
            s[j] = fminf((o1[j] + nn[j] * mul) * msk[j], o2[j]);
        float* sp = s_s + (ty * 8 + i) * AS_LD + tx * 8;
        *(float4*)sp = make_float4(s[0], s[1], s[2], s[3]);
        *(float4*)(sp + 4) = make_float4(s[4], s[5], s[6], s[7]);
    }
    __syncthreads();

    // Fused head: server[128,128] @ Ws[128,10] + bs  (one row per thread, 128 active)
    if (tid < BM) {
        const float* srow = s_s + tid * AS_LD;
        float p[10];
        #pragma unroll
        for (int c = 0; c < 10; c++) p[c] = 0.0f;
        #pragma unroll 4
        for (int k = 0; k < H_DIM; k++) {
            float sv = srow[k];
            float4 w0 = *(const float4*)&WsP[k * WSP_LD];
            float4 w1 = *(const float4*)&WsP[k * WSP_LD + 4];
            float2 w2 = *(const float2*)&WsP[k * WSP_LD + 8];
            p[0] = fmaf(sv, w0.x, p[0]); p[1] = fmaf(sv, w0.y, p[1]);
            p[2] = fmaf(sv, w0.z, p[2]); p[3] = fmaf(sv, w0.w, p[3]);
            p[4] = fmaf(sv, w1.x, p[4]); p[5] = fmaf(sv, w1.y, p[5]);
            p[6] = fmaf(sv, w1.z, p[6]); p[7] = fmaf(sv, w1.w, p[7]);
            p[8] = fmaf(sv, w2.x, p[8]); p[9] = fmaf(sv, w2.y, p[9]);
        }
        float* op = out + (size_t)(row0 + tid) * C_DIM;
        #pragma unroll
        for (int c = 0; c < 10; c++) op[c] = p[c] + bss[c];
    }
}

extern "C" void kernel_launch(void* const* d_in, const int* in_sizes, int n_in,
                              void* d_out, int out_size) {
    const float* x1    = (const float*)d_in[0];
    const float* x2    = (const float*)d_in[1];
    const float* W1    = (const float*)d_in[2];
    const float* b1    = (const float*)d_in[3];
    const float* W2    = (const float*)d_in[4];
    const float* b2    = (const float*)d_in[5];
    const float* Ws    = (const float*)d_in[6];
    const float* bs    = (const float*)d_in[7];
    const float* noise = (const float*)d_in[8];
    const float* rr    = (const float*)d_in[9];
    float* out = (float*)d_out;

    const int B = in_sizes[0] / F_DIM;   // 262144
    const int grid = B / BM;             // 2048

    cudaFuncSetAttribute(phase1_kernel,
                         cudaFuncAttributeMaxDynamicSharedMemorySize, SMEM1_BYTES);
    cudaFuncSetAttribute(phase2_kernel,
                         cudaFuncAttributeMaxDynamicSharedMemorySize, SMEM2_BYTES);

    init_minmax_kernel<<<1, 1>>>();
    phase1_kernel<<<grid, 256, SMEM1_BYTES>>>(x1, W1, b1);
    phase2_kernel<<<grid, 256, SMEM2_BYTES>>>(x2, W2, b2, Ws, bs, noise, rr, out);
}